// round 16
// baseline (speedup 1.0000x reference)
#include <cuda_runtime.h>

// ConvQuadInterp3d over x:(2,1,8,512,512) fp32.
// Output = coords_max (B,1,3,D,H,W) then y_max (B,1,D,H,W), fp32.
// Block = 32x4 tile. ALL 8 planes' halo (6x34x8 = 1632 floats, 6.4KB) staged
// into SMEM once (2 clamped LDG/thread/plane), ONE __syncthreads(), then a
// rolling-window mainloop reading LDS [reg + imm]. NMS via cached whole-plane
// 3x3 max scalars; the gradient/Hessian/solve block is branch-gated on the
// (~3.7%) NMS hit — legal now that the kernel is issue-bound (76%).

#define Dd 8
#define Hh 512
#define Ww 512
#define Bb 2
#define PLANE (Hh * Ww)
#define TW 32
#define TH 4
#define SROW 34
#define SPLN (6 * SROW)    // 204 floats per staged plane

__global__ void __launch_bounds__(128, 7)
conv_quad_interp3d_kernel(const float* __restrict__ x, float* __restrict__ out) {
    __shared__ float sm[Dd * SPLN];   // 1632 floats = 6528 B

    const int tdx = threadIdx.x, tdy = threadIdx.y;
    const int tid = tdy * TW + tdx;
    const int w0 = blockIdx.x * TW, h0 = blockIdx.y * TH;
    const int b = blockIdx.z;
    const int w = w0 + tdx, h = h0 + tdy;

    // ---- Prologue: stage all 8 planes; clamps (replicate pad) folded into two
    // precomputed global offsets, per-plane loads are [reg + p*PLANE imm].
    const int e0 = tid, e1 = tid + 128;
    const bool has1 = (e1 < SPLN);
    const int goff0 = min(max(h0 - 1 + e0 / SROW, 0), Hh - 1) * Ww
                    + min(max(w0 - 1 + e0 % SROW, 0), Ww - 1);
    const int goff1 = min(max(h0 - 1 + e1 / SROW, 0), Hh - 1) * Ww
                    + min(max(w0 - 1 + e1 % SROW, 0), Ww - 1);
    const float* xb = x + b * Dd * PLANE;

#pragma unroll
    for (int p = 0; p < Dd; p++) {
        sm[p * SPLN + e0] = __ldg(xb + p * PLANE + goff0);
        if (has1) sm[p * SPLN + e1] = __ldg(xb + p * PLANE + goff1);
    }
    __syncthreads();   // the only barrier

    const int sbase = tdy * SROW + tdx;

    // Read plane dn's 3x3 window; mx gets the whole-window max.
#define LOADP(dn, P, mx) do {                                                   \
    const int b_ = (dn) * SPLN + sbase;                                         \
    P[0] = sm[b_];            P[1] = sm[b_ + 1];          P[2] = sm[b_ + 2];    \
    P[3] = sm[b_ + SROW];     P[4] = sm[b_ + SROW + 1];   P[5] = sm[b_ + SROW + 2]; \
    P[6] = sm[b_ + 2*SROW];   P[7] = sm[b_ + 2*SROW + 1]; P[8] = sm[b_ + 2*SROW + 2]; \
    float m0_ = fmaxf(P[0], fmaxf(P[3], P[6]));                                 \
    float m1_ = fmaxf(P[1], fmaxf(P[4], P[7]));                                 \
    float m2_ = fmaxf(P[2], fmaxf(P[5], P[8]));                                 \
    mx = fmaxf(m0_, fmaxf(m1_, m2_));                                           \
} while (0)

    // Rolling window: P0 = plane d-1, C = d, N = d+1, with whole-plane maxima.
    float P0[9], C[9], N[9];
    float mP, mC, mN;

    LOADP(0, C, mC);
#pragma unroll
    for (int i = 0; i < 9; i++) P0[i] = C[i];
    mP = mC;                                           // replicate pad d = -1
    LOADP(1, N, mN);

    const float wf = (float)w, hf = (float)h;
    const int hw = h * Ww + w;
    float* pD = out + (b * 3 + 0) * Dd * PLANE + hw;
    float* pW = out + (b * 3 + 1) * Dd * PLANE + hw;
    float* pH = out + (b * 3 + 2) * Dd * PLANE + hw;
    float* pY = out + (Bb * 3) * Dd * PLANE + b * Dd * PLANE + hw;

#pragma unroll
    for (int d = 0; d < Dd; d++) {
        const float c = C[4];

        // NMS: max over 27 = max of the 3 cached whole-plane maxima.
        const float m = fmaxf(mP, fmaxf(mC, mN));
        const bool nms = (c == m);

        // Defaults for non-maximal voxels: refinement 0, y = c.
        float rx = 0.0f, ry = 0.0f, rs = 0.0f;
        float y = c;

        if (nms) {  // ~3.7% of voxels; ~30% of warps skip entirely
            // Gradients (central diff / 2, replicate pad)
            const float gx = 0.5f * (C[5] - C[3]);
            const float gy = 0.5f * (C[7] - C[1]);
            const float gs = 0.5f * (N[4] - P0[4]);

            // Hessian (cross terms * 0.25 per reference)
            const float axx = C[3] + C[5] - 2.0f * c;
            const float ayy = C[1] + C[7] - 2.0f * c;
            const float ass = P0[4] + N[4] - 2.0f * c;
            const float axy = 0.25f * (C[0] + C[8] - C[6] - C[2]);
            const float ays = 0.25f * (P0[1] + N[7] - N[1] - P0[7]);
            const float axs = 0.25f * (P0[3] + N[5] - N[3] - P0[5]);

            // Symmetric 3x3 solve via adjugate (Cramer)
            const float c00 = ayy * ass - ays * ays;
            const float c01 = axs * ays - axy * ass;
            const float c02 = axy * ays - axs * ayy;
            const float det = axx * c00 + axy * c01 + axs * c02;

            if (det != 0.0f) {
                const float inv = 1.0f / det;
                const float c11 = axx * ass - axs * axs;
                const float c12 = axy * axs - axx * ays;
                const float c22 = axx * ayy - axy * axy;
                rx = -(c00 * gx + c01 * gy + c02 * gs) * inv;
                ry = -(c01 * gx + c11 * gy + c12 * gs) * inv;
                rs = -(c02 * gx + c12 * gy + c22 * gs) * inv;
                const float big = fmaxf(fabsf(rx), fmaxf(fabsf(ry), fabsf(rs)));
                if (big > 0.7f) { rx = 0.0f; ry = 0.0f; rs = 0.0f; }
                const float dyv = 0.5f * (gx * rx + gy * ry + gs * rs);
                y = c + dyv + 10.0f;   // strict-maxima bonus only when solved
            }
        }

        // coords channels: grid(d, w, h) + flipped refinement (s, y, x)
        pD[d * PLANE] = (float)d + rs;
        pW[d * PLANE] = wf + ry;
        pH[d * PLANE] = hf + rx;
        pY[d * PLANE] = y;

        if (d < Dd - 1) {
#pragma unroll
            for (int i = 0; i < 9; i++) { P0[i] = C[i]; C[i] = N[i]; }
            mP = mC; mC = mN;
            // Skip the tail reload: after the shift N already holds plane 7,
            // which equals the replicate pad for d+1 = 8.
            if (d + 2 < Dd) LOADP(d + 2, N, mN);
        }
    }
}

extern "C" void kernel_launch(void* const* d_in, const int* in_sizes, int n_in,
                              void* d_out, int out_size) {
    const float* x = (const float*)d_in[0];
    float* out = (float*)d_out;
    dim3 block(TW, TH, 1);
    dim3 grid(Ww / TW, Hh / TH, Bb);  // (16, 128, 2)
    conv_quad_interp3d_kernel<<<grid, block>>>(x, out);
}

// round 17
// speedup vs baseline: 1.1050x; 1.1050x over previous
#include <cuda_runtime.h>

// ConvQuadInterp3d over x:(2,1,8,512,512) fp32.
// Output = coords_max (B,1,3,D,H,W) then y_max (B,1,D,H,W), fp32.
// Block = 32x4 threads, each thread owns 2 consecutive w (tile 64x4).
// ALL 8 planes' halo (6x66 = 396 floats/plane, 12.7KB) staged into SMEM once,
// ONE __syncthreads(), then a rolling-window mainloop whose plane reads are
// 6x LDS.64 (aligned float2, conflict-free). Outputs stored as STG.64.
// Solve block branch-gated on the ~3.7% NMS hit (issue-bound regime).

#define Dd 8
#define Hh 512
#define Ww 512
#define Bb 2
#define PLANE (Hh * Ww)
#define TH 4
#define SROW 66
#define SPLN (6 * SROW)    // 396 floats per staged plane

__global__ void __launch_bounds__(128, 6)
conv_quad_interp3d_kernel(const float* __restrict__ x, float* __restrict__ out) {
    __shared__ float sm[Dd * SPLN];   // 3168 floats = 12672 B

    const int tdx = threadIdx.x, tdy = threadIdx.y;
    const int tid = tdy * 32 + tdx;
    const int wb = blockIdx.x * 64;        // tile base w (tile is 64 wide)
    const int h0 = blockIdx.y * TH;
    const int b  = blockIdx.z;
    const int w0 = wb + 2 * tdx;           // this thread's first voxel w (even)
    const int h  = h0 + tdy;

    // ---- Prologue: stage all 8 planes. 396 elems/plane, 128 threads:
    // k = 0..2 full, k = 3 only tid < 12. Replicate-pad clamps folded into
    // precomputed global offsets; per-plane loads are [reg + p*PLANE imm].
    const float* xb = x + b * Dd * PLANE;
    int goff[4];
#pragma unroll
    for (int k = 0; k < 4; k++) {
        const int e = tid + 128 * k;
        const int r = e / SROW, cc = e % SROW;
        goff[k] = min(max(h0 - 1 + r, 0), Hh - 1) * Ww
                + min(max(wb - 1 + cc, 0), Ww - 1);
    }
#pragma unroll
    for (int p = 0; p < Dd; p++) {
        sm[p * SPLN + tid]       = __ldg(xb + p * PLANE + goff[0]);
        sm[p * SPLN + tid + 128] = __ldg(xb + p * PLANE + goff[1]);
        sm[p * SPLN + tid + 256] = __ldg(xb + p * PLANE + goff[2]);
        if (tid < SPLN - 384)
            sm[p * SPLN + tid + 384] = __ldg(xb + p * PLANE + goff[3]);
    }
    __syncthreads();   // the only barrier

    // Plane read: 12 values (3 rows x cols [w0-1 .. w0+2]) via 6 aligned LDS.64.
    // Halo col index of w0-1 is 2*tdx (even) -> float2 index tdx within the row.
    const float2* s2 = reinterpret_cast<const float2*>(sm);

#define LOADP(dn, V, t) do {                                                    \
    _Pragma("unroll")                                                           \
    for (int r_ = 0; r_ < 3; r_++) {                                            \
        const int f2 = ((dn) * SPLN + (tdy + r_) * SROW) / 2 + tdx;             \
        const float2 a_ = s2[f2];                                               \
        const float2 b_ = s2[f2 + 1];                                           \
        V[r_ * 4 + 0] = a_.x; V[r_ * 4 + 1] = a_.y;                             \
        V[r_ * 4 + 2] = b_.x; V[r_ * 4 + 3] = b_.y;                             \
    }                                                                           \
    {                                                                           \
        const float c0_ = fmaxf(V[0], fmaxf(V[4], V[8]));                       \
        const float c1_ = fmaxf(V[1], fmaxf(V[5], V[9]));                       \
        const float c2_ = fmaxf(V[2], fmaxf(V[6], V[10]));                      \
        const float c3_ = fmaxf(V[3], fmaxf(V[7], V[11]));                      \
        const float m_  = fmaxf(c1_, c2_);                                      \
        t[0] = fmaxf(c0_, m_);                                                  \
        t[1] = fmaxf(m_, c3_);                                                  \
    }                                                                           \
} while (0)

    // Rolling window: P0 = plane d-1, C = d, N = d+1, with per-voxel NMS triples.
    float P0[12], C[12], N[12];
    float tP[2], tC[2], tN[2];

    LOADP(0, C, tC);
#pragma unroll
    for (int i = 0; i < 12; i++) P0[i] = C[i];
    tP[0] = tC[0]; tP[1] = tC[1];                  // replicate pad d = -1
    LOADP(1, N, tN);

    const float wf = (float)w0, hf = (float)h;
    const int hw = h * Ww + w0;
    float* pD = out + (b * 3 + 0) * Dd * PLANE + hw;
    float* pW = out + (b * 3 + 1) * Dd * PLANE + hw;
    float* pH = out + (b * 3 + 2) * Dd * PLANE + hw;
    float* pY = out + (Bb * 3) * Dd * PLANE + b * Dd * PLANE + hw;

#pragma unroll
    for (int d = 0; d < Dd; d++) {
        float rD[2], rW[2], rH[2], rY[2];

#pragma unroll
        for (int j = 0; j < 2; j++) {
            const float c = C[4 + j + 1];

            // NMS: max over 27 = max of the 3 cached per-plane triples.
            const float m = fmaxf(tP[j], fmaxf(tC[j], tN[j]));
            const bool nms = (c == m);

            float rx = 0.0f, ry = 0.0f, rs = 0.0f;
            float y = c;

            if (nms) {  // ~3.7% of voxels
                // Gradients (central diff / 2, replicate pad)
                const float gx = 0.5f * (C[4 + j + 2] - C[4 + j]);
                const float gy = 0.5f * (C[8 + j + 1] - C[j + 1]);
                const float gs = 0.5f * (N[4 + j + 1] - P0[4 + j + 1]);

                // Hessian (cross terms * 0.25 per reference)
                const float axx = C[4 + j] + C[4 + j + 2] - 2.0f * c;
                const float ayy = C[j + 1] + C[8 + j + 1] - 2.0f * c;
                const float ass = P0[4 + j + 1] + N[4 + j + 1] - 2.0f * c;
                const float axy = 0.25f * (C[j] + C[8 + j + 2] - C[8 + j] - C[j + 2]);
                const float ays = 0.25f * (P0[j + 1] + N[8 + j + 1] - N[j + 1] - P0[8 + j + 1]);
                const float axs = 0.25f * (P0[4 + j] + N[4 + j + 2] - N[4 + j] - P0[4 + j + 2]);

                // Symmetric 3x3 solve via adjugate (Cramer)
                const float c00 = ayy * ass - ays * ays;
                const float c01 = axs * ays - axy * ass;
                const float c02 = axy * ays - axs * ayy;
                const float det = axx * c00 + axy * c01 + axs * c02;

                if (det != 0.0f) {
                    const float inv = 1.0f / det;
                    const float c11 = axx * ass - axs * axs;
                    const float c12 = axy * axs - axx * ays;
                    const float c22 = axx * ayy - axy * axy;
                    rx = -(c00 * gx + c01 * gy + c02 * gs) * inv;
                    ry = -(c01 * gx + c11 * gy + c12 * gs) * inv;
                    rs = -(c02 * gx + c12 * gy + c22 * gs) * inv;
                    const float big = fmaxf(fabsf(rx), fmaxf(fabsf(ry), fabsf(rs)));
                    if (big > 0.7f) { rx = 0.0f; ry = 0.0f; rs = 0.0f; }
                    const float dyv = 0.5f * (gx * rx + gy * ry + gs * rs);
                    y = c + dyv + 10.0f;   // strict-maxima bonus only when solved
                }
            }

            rY[j] = y;
            // grid channels (d, w, h) + flipped refinement (s, y, x)
            rD[j] = (float)d + rs;
            rW[j] = (wf + (float)j) + ry;
            rH[j] = hf + rx;
        }

        *reinterpret_cast<float2*>(pD + d * PLANE) = make_float2(rD[0], rD[1]);
        *reinterpret_cast<float2*>(pW + d * PLANE) = make_float2(rW[0], rW[1]);
        *reinterpret_cast<float2*>(pH + d * PLANE) = make_float2(rH[0], rH[1]);
        *reinterpret_cast<float2*>(pY + d * PLANE) = make_float2(rY[0], rY[1]);

        if (d < Dd - 1) {
#pragma unroll
            for (int i = 0; i < 12; i++) { P0[i] = C[i]; C[i] = N[i]; }
            tP[0] = tC[0]; tP[1] = tC[1];
            tC[0] = tN[0]; tC[1] = tN[1];
            // Tail: after the shift N already holds plane 7 = replicate pad at d=8.
            if (d + 2 < Dd) LOADP(d + 2, N, tN);
        }
    }
}

extern "C" void kernel_launch(void* const* d_in, const int* in_sizes, int n_in,
                              void* d_out, int out_size) {
    const float* x = (const float*)d_in[0];
    float* out = (float*)d_out;
    dim3 block(32, TH, 1);
    dim3 grid(Ww / 64, Hh / TH, Bb);  // (8, 128, 2) = 2048 blocks
    conv_quad_interp3d_kernel<<<grid, block>>>(x, out);
}